// round 17
// baseline (speedup 1.0000x reference)
#include <cuda_runtime.h>
#include <cstdint>

// Problem constants (fixed by setup_inputs)
#define B_  64
#define NO_ 1024
#define NI_ 1024
#define NBT 8                          // batches per block (one per warp)
#define BSTRIDE (NO_ * NI_)            // elements between consecutive batches

// RHO_R = exp(-DT/TAU_R) = exp(-0.05)
__device__ __constant__ float kRhoR = 0.95122942450071400910f;

// Warp-autonomous variant: block = (j, 8-batch tile), 8 warps; warp w owns
// batch b0+w's ENTIRE row (32 lanes x 8 float4 chunks = 1024 elements).
//  - rho/w staged into smem once per block (single EARLY barrier, before any
//    long-latency consumption; no late barrier -> warps finish independently)
//  - hIsyn front-batched per thread (8 __ldcs in flight) BEFORE the barrier
//  - row sum is intra-warp only: 5 shuffles total, no wsum smem round trip
__global__ void __launch_bounds__(256, 4)
hetsyn_cell_kernel(const float* __restrict__ x,      // (B, NI)
                   const float* __restrict__ w,      // (NO, NI)
                   const float* __restrict__ rho,    // (NO, NI)
                   const float* __restrict__ hz,     // (B, NO)
                   const float* __restrict__ hIsyn,  // (B, NO, NI)
                   const float* __restrict__ hIr,    // (B, NO)
                   float* __restrict__ z_out,        // (B, NO)
                   float* __restrict__ Isyn_out,     // (B, NO, NI)
                   float* __restrict__ Ir_out)       // (B, NO)
{
    __shared__ __align__(16) float s_rho[NI_];   // 4 KB
    __shared__ __align__(16) float s_w[NI_];     // 4 KB

    const int j    = blockIdx.x;         // output neuron row
    const int b0   = blockIdx.y * NBT;   // first batch of this tile
    const int t    = threadIdx.x;        // 0..255
    const int lane = t & 31;
    const int warp = t >> 5;             // owns batch b0+warp
    const int b    = b0 + warp;

    // ---- Front-batch this warp's 8 streaming loads (MLP=8, issued first) ----
    // Warp w reads row (b, j): chunk c covers elements [c*128, c*128+128),
    // lane handles float4 at index c*32+lane (fully coalesced).
    const size_t rowb = ((size_t)(b * NO_ + j) << 10);
    const float4* hbase = reinterpret_cast<const float4*>(hIsyn) + (rowb >> 2) + lane;
    float4 hv[8];
    #pragma unroll
    for (int c = 0; c < 8; ++c)
        hv[c] = __ldcs(hbase + c * 32);

    asm volatile("" ::: "memory");   // keep smem staging below the burst

    // ---- Stage rho/w rows into smem (cooperative, L2 hits) ----
    {
        const float4* rsrc = reinterpret_cast<const float4*>(rho) + ((size_t)j << 8) + t;
        const float4* wsrc = reinterpret_cast<const float4*>(w)   + ((size_t)j << 8) + t;
        reinterpret_cast<float4*>(s_rho)[t] = __ldg(rsrc);
        reinterpret_cast<float4*>(s_w)[t]   = __ldg(wsrc);
    }

    // Epilogue prefetch (lane 0 only; resolves while compute runs)
    const int oidx = b * NO_ + j;
    float Ir_pre = 0.0f;
    if (lane == 0)
        Ir_pre = fmaf(kRhoR, __ldg(hIr + oidx), __ldg(hz + oidx));

    __syncthreads();   // single EARLY barrier; warps independent after this

    // ---- Compute: per chunk, smem rho/w + L2-hit x, FMA, streaming store ----
    const float4* xbase = reinterpret_cast<const float4*>(x) + ((size_t)b << 8) + lane;
    float4*       qbase = reinterpret_cast<float4*>(Isyn_out) + (rowb >> 2) + lane;
    const float4* s_r4  = reinterpret_cast<const float4*>(s_rho) + lane;
    const float4* s_w4  = reinterpret_cast<const float4*>(s_w)   + lane;

    float psum = 0.0f;
    #pragma unroll
    for (int c = 0; c < 8; ++c) {
        const float4 rv = s_r4[c * 32];
        const float4 wv = s_w4[c * 32];
        const float4 xv = __ldg(xbase + c * 32);

        float4 Is;
        Is.x = fmaf(rv.x, hv[c].x, wv.x * xv.x);
        Is.y = fmaf(rv.y, hv[c].y, wv.y * xv.y);
        Is.z = fmaf(rv.z, hv[c].z, wv.z * xv.z);
        Is.w = fmaf(rv.w, hv[c].w, wv.w * xv.w);

        __stcs(qbase + c * 32, Is);

        psum += (Is.x + Is.y) + (Is.z + Is.w);
    }

    // ---- Intra-warp row sum (5 shuffles), then neuron update by lane 0 ----
    #pragma unroll
    for (int off = 16; off > 0; off >>= 1)
        psum += __shfl_down_sync(0xFFFFFFFFu, psum, off);

    if (lane == 0) {
        Ir_out[oidx] = Ir_pre;
        // v = psum - THR*Ir; z = (v - THR >= 0), THR = 1
        z_out[oidx]  = (psum - Ir_pre - 1.0f >= 0.0f) ? 1.0f : 0.0f;
    }
}

extern "C" void kernel_launch(void* const* d_in, const int* in_sizes, int n_in,
                              void* d_out, int out_size)
{
    // Input order per setup_inputs: x, w, rho, hz, hIsyn, hIr
    const float* x     = (const float*)d_in[0];
    const float* w     = (const float*)d_in[1];
    const float* rho   = (const float*)d_in[2];
    const float* hz    = (const float*)d_in[3];
    const float* hIsyn = (const float*)d_in[4];
    const float* hIr   = (const float*)d_in[5];

    // Output tuple (z, Isyn, Ir) flattened + concatenated
    float* out    = (float*)d_out;
    float* z_out  = out;
    float* Isyn_o = out + (size_t)B_ * NO_;
    float* Ir_out = out + (size_t)B_ * NO_ + (size_t)B_ * NO_ * NI_;

    dim3 grid(NO_, B_ / NBT);   // (1024, 8) = 8192 blocks, multi-wave
    dim3 block(256);
    hetsyn_cell_kernel<<<grid, block>>>(x, w, rho, hz, hIsyn, hIr,
                                        z_out, Isyn_o, Ir_out);
}